// round 16
// baseline (speedup 1.0000x reference)
#include <cuda_runtime.h>

// All-pairs N-body gravity — single graph node, lean finalize protocol.
// R15 measured single-node replay gap = 0.6us (vs 3.3 two-node) but its
// protocol cost +4.9us, dominated by 2048 CTAs' gpu-scope threadfences
// (each drains ~318cyc in-flight REDGs) landing in the tail. Fix: JCHUNK=256
// -> 512 CTAs (4x fewer fences, 4x amortization) and a merged copy+reset
// finalizer via atomicExch (one L2 op, no second fence, no reset stores).
// Inner loop = byte-identical R5/R11 packed-f32x2 IPT=2 (36.0us, 3x repro).

#define BLOCK  256
#define IPT    2
#define JCHUNK 256
#define JP     (JCHUNK / 2)
#define NJB    32               // j-blocks = 8192 / JCHUNK
#define NIB    16               // i-blocks = 8192 / (BLOCK*IPT)
#define EPS2   0.0001f          // SOFTENING^2

typedef unsigned long long u64;

__device__ float        g_scratch[8192 * 3];   // zero-initialized at load
__device__ unsigned int g_count[NIB];          // zero-initialized at load

__device__ __forceinline__ u64 pack2(float lo, float hi) {
    u64 r;
    asm("mov.b64 %0, {%1, %2};" : "=l"(r)
        : "r"(__float_as_uint(lo)), "r"(__float_as_uint(hi)));
    return r;
}
__device__ __forceinline__ void unpack2(u64 v, float& lo, float& hi) {
    unsigned a, b;
    asm("mov.b64 {%0, %1}, %2;" : "=r"(a), "=r"(b) : "l"(v));
    lo = __uint_as_float(a);
    hi = __uint_as_float(b);
}
__device__ __forceinline__ u64 f2add(u64 a, u64 b) {
    u64 r; asm("add.rn.f32x2 %0, %1, %2;" : "=l"(r) : "l"(a), "l"(b)); return r;
}
__device__ __forceinline__ u64 f2mul(u64 a, u64 b) {
    u64 r; asm("mul.rn.f32x2 %0, %1, %2;" : "=l"(r) : "l"(a), "l"(b)); return r;
}
__device__ __forceinline__ u64 f2fma(u64 a, u64 b, u64 c) {
    u64 r; asm("fma.rn.f32x2 %0, %1, %2, %3;"
               : "=l"(r) : "l"(a), "l"(b), "l"(c)); return r;
}
__device__ __forceinline__ float rsq_mufu(float x) {
    float r; asm("rsqrt.approx.f32 %0, %1;" : "=f"(r) : "f"(x)); return r;
}

__global__ __launch_bounds__(BLOCK)
void nbody_forces_kernel(const float* __restrict__ pos,
                         const float* __restrict__ mass,
                         float* __restrict__ out) {
    __shared__ u64 sx[JP], sy[JP], sz[JP], sm[JP];
    __shared__ int s_last;

    const int tid   = threadIdx.x;
    const int i0    = blockIdx.x * (BLOCK * IPT) + tid;
    const int i1    = i0 + BLOCK;
    const int jbase = blockIdx.y * JCHUNK;

    {   // stage one j per thread (JCHUNK == BLOCK)
        int j = jbase + tid;
        ((float*)sx)[tid] = pos[3 * j + 0];
        ((float*)sy)[tid] = pos[3 * j + 1];
        ((float*)sz)[tid] = pos[3 * j + 2];
        ((float*)sm)[tid] = mass[j];
    }
    __syncthreads();

    const u64 nx0 = pack2(-pos[3 * i0 + 0], -pos[3 * i0 + 0]);
    const u64 ny0 = pack2(-pos[3 * i0 + 1], -pos[3 * i0 + 1]);
    const u64 nz0 = pack2(-pos[3 * i0 + 2], -pos[3 * i0 + 2]);
    const u64 nx1 = pack2(-pos[3 * i1 + 0], -pos[3 * i1 + 0]);
    const u64 ny1 = pack2(-pos[3 * i1 + 1], -pos[3 * i1 + 1]);
    const u64 nz1 = pack2(-pos[3 * i1 + 2], -pos[3 * i1 + 2]);
    const u64 eps22 = pack2(EPS2, EPS2);

    u64 ax0 = 0ull, ay0 = 0ull, az0 = 0ull;
    u64 ax1 = 0ull, ay1 = 0ull, az1 = 0ull;

#pragma unroll 4
    for (int t = 0; t < JP; ++t) {
        const u64 px = sx[t];              // LDS.64 broadcast feeds 4 pairs
        const u64 py = sy[t];
        const u64 pz = sz[t];
        const u64 pm = sm[t];

        u64 dx0 = f2add(px, nx0);
        u64 dy0 = f2add(py, ny0);
        u64 dz0 = f2add(pz, nz0);
        u64 dx1 = f2add(px, nx1);
        u64 dy1 = f2add(py, ny1);
        u64 dz1 = f2add(pz, nz1);

        u64 r20 = f2fma(dx0, dx0, f2fma(dy0, dy0, f2fma(dz0, dz0, eps22)));
        u64 r21 = f2fma(dx1, dx1, f2fma(dy1, dy1, f2fma(dz1, dz1, eps22)));

        float a, b;
        unpack2(r20, a, b);
        u64 inv0 = pack2(rsq_mufu(a), rsq_mufu(b));
        unpack2(r21, a, b);
        u64 inv1 = pack2(rsq_mufu(a), rsq_mufu(b));

        u64 s0 = f2mul(pm, f2mul(f2mul(inv0, inv0), inv0));
        u64 s1 = f2mul(pm, f2mul(f2mul(inv1, inv1), inv1));

        ax0 = f2fma(s0, dx0, ax0);
        ay0 = f2fma(s0, dy0, ay0);
        az0 = f2fma(s0, dz0, az0);
        ax1 = f2fma(s1, dx1, ax1);
        ay1 = f2fma(s1, dy1, ay1);
        az1 = f2fma(s1, dz1, az1);
    }

    // Partials into persistent scratch (zero by invariant).
    float l, h;
    unpack2(ax0, l, h); atomicAdd(&g_scratch[3 * i0 + 0], l + h);
    unpack2(ay0, l, h); atomicAdd(&g_scratch[3 * i0 + 1], l + h);
    unpack2(az0, l, h); atomicAdd(&g_scratch[3 * i0 + 2], l + h);
    unpack2(ax1, l, h); atomicAdd(&g_scratch[3 * i1 + 0], l + h);
    unpack2(ay1, l, h); atomicAdd(&g_scratch[3 * i1 + 1], l + h);
    unpack2(az1, l, h); atomicAdd(&g_scratch[3 * i1 + 2], l + h);

    // Release: make this CTA's adds visible before the counter bump.
    __threadfence();
    __syncthreads();
    if (tid == 0) {
        unsigned prev = atomicAdd(&g_count[blockIdx.x], 1u);
        s_last = (prev == NJB - 1u);
    }
    __syncthreads();

    // Last j-CTA of this i-block: merged copy+reset via atomicExch (L2-
    // coherent read of the accumulated value, zeroing for the next replay).
    if (s_last) {
        const int base = blockIdx.x * (BLOCK * IPT) * 3;   // 1536 floats
#pragma unroll
        for (int q = 0; q < 6; ++q) {
            const int idx = base + q * BLOCK + tid;
            out[idx] = atomicExch(&g_scratch[idx], 0.0f);
        }
        if (tid == 0) g_count[blockIdx.x] = 0u;
    }
}

extern "C" void kernel_launch(void* const* d_in, const int* in_sizes, int n_in,
                              void* d_out, int out_size) {
    const float* pos  = (const float*)d_in[0];   // [N,3] float32
    const float* mass = (const float*)d_in[1];   // [N]   float32
    float* out = (float*)d_out;                  // [N,3] float32

    const int n = in_sizes[0] / 3;               // 8192

    dim3 grid(n / (BLOCK * IPT), n / JCHUNK);    // 16 x 32 = 512 CTAs
    nbody_forces_kernel<<<grid, BLOCK>>>(pos, mass, out);   // single node
}

// round 17
// speedup vs baseline: 1.0982x; 1.0982x over previous
#include <cuda_runtime.h>

// All-pairs N-body gravity — single graph node, FENCE-FREE finalize.
// Ledger: two-node floor = 36.0 kernel + 3.3 node gap = 39.3 (can't beat).
// Single-node gap = 0.6us, but R15's __threadfence protocol cost +4.9us
// (2048 CTAs x 256-thread gpu-scope MEMBAR). Fix: prove visibility by
// DATAFLOW — atomicAdd WITH consumed return (ATOMG): once the old value is
// in a register the op has executed at L2. asm barrier keeps the dependency,
// __syncthreads orders all threads, then one counter bump. Last j-CTA per
// i-block copies scratch->out and re-zeros via atomicExch (invariant for
// next replay). Main loop = R11's proven 36.1us config, byte-identical.

#define BLOCK  256
#define IPT    2
#define JCHUNK 64
#define JP     (JCHUNK / 2)
#define NJB    128              // j-blocks = 8192 / JCHUNK
#define NIB    16               // i-blocks = 8192 / (BLOCK*IPT)
#define EPS2   0.0001f          // SOFTENING^2

typedef unsigned long long u64;

__device__ float        g_scratch[8192 * 3];   // zero-initialized at load
__device__ unsigned int g_count[NIB];          // zero-initialized at load

__device__ __forceinline__ u64 pack2(float lo, float hi) {
    u64 r;
    asm("mov.b64 %0, {%1, %2};" : "=l"(r)
        : "r"(__float_as_uint(lo)), "r"(__float_as_uint(hi)));
    return r;
}
__device__ __forceinline__ void unpack2(u64 v, float& lo, float& hi) {
    unsigned a, b;
    asm("mov.b64 {%0, %1}, %2;" : "=r"(a), "=r"(b) : "l"(v));
    lo = __uint_as_float(a);
    hi = __uint_as_float(b);
}
__device__ __forceinline__ u64 f2add(u64 a, u64 b) {
    u64 r; asm("add.rn.f32x2 %0, %1, %2;" : "=l"(r) : "l"(a), "l"(b)); return r;
}
__device__ __forceinline__ u64 f2mul(u64 a, u64 b) {
    u64 r; asm("mul.rn.f32x2 %0, %1, %2;" : "=l"(r) : "l"(a), "l"(b)); return r;
}
__device__ __forceinline__ u64 f2fma(u64 a, u64 b, u64 c) {
    u64 r; asm("fma.rn.f32x2 %0, %1, %2, %3;"
               : "=l"(r) : "l"(a), "l"(b), "l"(c)); return r;
}
__device__ __forceinline__ float rsq_mufu(float x) {
    float r; asm("rsqrt.approx.f32 %0, %1;" : "=f"(r) : "f"(x)); return r;
}

__global__ __launch_bounds__(BLOCK)
void nbody_forces_kernel(const float* __restrict__ pos,
                         const float* __restrict__ mass,
                         float* __restrict__ out) {
    __shared__ u64 sx[JP], sy[JP], sz[JP], sm[JP];
    __shared__ int s_last;

    const int tid   = threadIdx.x;
    const int i0    = blockIdx.x * (BLOCK * IPT) + tid;
    const int i1    = i0 + BLOCK;
    const int jbase = blockIdx.y * JCHUNK;

    if (tid < JCHUNK) {
        int j = jbase + tid;
        ((float*)sx)[tid] = pos[3 * j + 0];
        ((float*)sy)[tid] = pos[3 * j + 1];
        ((float*)sz)[tid] = pos[3 * j + 2];
        ((float*)sm)[tid] = mass[j];
    }
    __syncthreads();

    const u64 nx0 = pack2(-pos[3 * i0 + 0], -pos[3 * i0 + 0]);
    const u64 ny0 = pack2(-pos[3 * i0 + 1], -pos[3 * i0 + 1]);
    const u64 nz0 = pack2(-pos[3 * i0 + 2], -pos[3 * i0 + 2]);
    const u64 nx1 = pack2(-pos[3 * i1 + 0], -pos[3 * i1 + 0]);
    const u64 ny1 = pack2(-pos[3 * i1 + 1], -pos[3 * i1 + 1]);
    const u64 nz1 = pack2(-pos[3 * i1 + 2], -pos[3 * i1 + 2]);
    const u64 eps22 = pack2(EPS2, EPS2);

    u64 ax0 = 0ull, ay0 = 0ull, az0 = 0ull;
    u64 ax1 = 0ull, ay1 = 0ull, az1 = 0ull;

#pragma unroll 4
    for (int t = 0; t < JP; ++t) {
        const u64 px = sx[t];              // LDS.64 broadcast feeds 4 pairs
        const u64 py = sy[t];
        const u64 pz = sz[t];
        const u64 pm = sm[t];

        u64 dx0 = f2add(px, nx0);
        u64 dy0 = f2add(py, ny0);
        u64 dz0 = f2add(pz, nz0);
        u64 dx1 = f2add(px, nx1);
        u64 dy1 = f2add(py, ny1);
        u64 dz1 = f2add(pz, nz1);

        u64 r20 = f2fma(dx0, dx0, f2fma(dy0, dy0, f2fma(dz0, dz0, eps22)));
        u64 r21 = f2fma(dx1, dx1, f2fma(dy1, dy1, f2fma(dz1, dz1, eps22)));

        float a, b;
        unpack2(r20, a, b);
        u64 inv0 = pack2(rsq_mufu(a), rsq_mufu(b));
        unpack2(r21, a, b);
        u64 inv1 = pack2(rsq_mufu(a), rsq_mufu(b));

        u64 s0 = f2mul(pm, f2mul(f2mul(inv0, inv0), inv0));
        u64 s1 = f2mul(pm, f2mul(f2mul(inv1, inv1), inv1));

        ax0 = f2fma(s0, dx0, ax0);
        ay0 = f2fma(s0, dy0, ay0);
        az0 = f2fma(s0, dz0, az0);
        ax1 = f2fma(s1, dx1, ax1);
        ay1 = f2fma(s1, dy1, ay1);
        az1 = f2fma(s1, dz1, az1);
    }

    // Partials into persistent scratch via ATOMG (returns consumed -> op
    // proven executed at L2 when the return lands; no membar needed).
    float l, h;
    float d0, d1, d2, d3, d4, d5;
    unpack2(ax0, l, h); d0 = atomicAdd(&g_scratch[3 * i0 + 0], l + h);
    unpack2(ay0, l, h); d1 = atomicAdd(&g_scratch[3 * i0 + 1], l + h);
    unpack2(az0, l, h); d2 = atomicAdd(&g_scratch[3 * i0 + 2], l + h);
    unpack2(ax1, l, h); d3 = atomicAdd(&g_scratch[3 * i1 + 0], l + h);
    unpack2(ay1, l, h); d4 = atomicAdd(&g_scratch[3 * i1 + 1], l + h);
    unpack2(az1, l, h); d5 = atomicAdd(&g_scratch[3 * i1 + 2], l + h);
    // Force the returns to be materialized (keeps ATOM form + ordering).
    float dep = (d0 + d1) + (d2 + d3) + (d4 + d5);
    asm volatile("" :: "f"(dep) : "memory");

    // All threads' adds are at L2; barrier, then one counter bump.
    __syncthreads();
    if (tid == 0) {
        unsigned prev = atomicAdd(&g_count[blockIdx.x], 1u);
        s_last = (prev == NJB - 1u);
    }
    __syncthreads();

    // Last j-CTA of this i-block: merged copy + re-zero via atomicExch.
    if (s_last) {
        const int base = blockIdx.x * (BLOCK * IPT) * 3;   // 1536 floats
#pragma unroll
        for (int q = 0; q < 6; ++q) {
            const int idx = base + q * BLOCK + tid;
            out[idx] = atomicExch(&g_scratch[idx], 0.0f);
        }
        if (tid == 0) g_count[blockIdx.x] = 0u;
    }
}

extern "C" void kernel_launch(void* const* d_in, const int* in_sizes, int n_in,
                              void* d_out, int out_size) {
    const float* pos  = (const float*)d_in[0];   // [N,3] float32
    const float* mass = (const float*)d_in[1];   // [N]   float32
    float* out = (float*)d_out;                  // [N,3] float32

    const int n = in_sizes[0] / 3;               // 8192

    dim3 grid(n / (BLOCK * IPT), n / JCHUNK);    // 16 x 128 = 2048 CTAs
    nbody_forces_kernel<<<grid, BLOCK>>>(pos, mass, out);   // single node
}